// round 14
// baseline (speedup 1.0000x reference)
#include <cuda_runtime.h>
#include <cuda_bf16.h>
#include <cuda_fp16.h>
#include <cstdint>

#define B_ 8
#define N_ 200
#define D_ 128
#define BN_ (B_ * N_)            // 1600
#define HSZ (B_ * N_ * D_)       // 204800
#define ESZ (B_ * N_ * N_ * D_)  // 40960000
#define EPS 1e-5f
#define EBLKS (ESZ / 4 / 256)    // 40000
#define HBLKS (HSZ / 4 / 256)    // 200

// ---------------- scratch (device globals, no allocation) ----------------
__device__ float g_Uh[HSZ];
__device__ float g_Vh[HSZ];
__device__ float g_Ah[HSZ];
__device__ float g_Bh[HSZ];
__device__ float g_hnew[HSZ];
__device__ __align__(16) __half g_x[ESZ];   // fp16 e_new scratch (82 MB)
__device__ float g_acc[4 * D_];   // e_sum, e_sqsum, h_sum, h_sqsum
__device__ float g_coef[4 * D_];  // scale_e, shift_e, scale_h, shift_h
__device__ uint32_t g_CwH[D_ * 64];  // bf16-pair-packed Cw hi, [d][kword]
__device__ uint32_t g_CwL[D_ * 64];  // bf16-pair-packed Cw lo, [d][kword]
__device__ unsigned int g_done;

// ================= helpers ===========================================
__device__ __forceinline__ uint32_t pack_bf(float x, float y) {
    __nv_bfloat162 p = __floats2bfloat162_rn(x, y);
    return *reinterpret_cast<uint32_t*>(&p);
}

__device__ __forceinline__ void mma16816(float* c,
                                         uint32_t a0, uint32_t a1, uint32_t a2, uint32_t a3,
                                         uint32_t b0, uint32_t b1) {
    asm volatile(
        "mma.sync.aligned.m16n8k16.row.col.f32.bf16.bf16.f32 "
        "{%0,%1,%2,%3}, {%4,%5,%6,%7}, {%8,%9}, {%0,%1,%2,%3};"
        : "+f"(c[0]), "+f"(c[1]), "+f"(c[2]), "+f"(c[3])
        : "r"(a0), "r"(a1), "r"(a2), "r"(a3), "r"(b0), "r"(b1));
}

__device__ __forceinline__ void ldmx4(uint32_t& r0, uint32_t& r1, uint32_t& r2, uint32_t& r3,
                                      uint32_t saddr) {
    asm volatile("ldmatrix.sync.aligned.m8n8.x4.shared.b16 {%0,%1,%2,%3}, [%4];"
                 : "=r"(r0), "=r"(r1), "=r"(r2), "=r"(r3) : "r"(saddr));
}

__device__ __forceinline__ uint32_t smem_u32(const void* p) {
    uint32_t a;
    asm("{ .reg .u64 t; cvta.to.shared.u64 t, %1; cvt.u32.u64 %0, t; }" : "=r"(a) : "l"(p));
    return a;
}
#define BAR_SYNC(id, cnt) asm volatile("bar.sync %0, %1;" :: "r"(id), "r"(cnt) : "memory")
#define BAR_ARRIVE(id, cnt) asm volatile("bar.arrive %0, %1;" :: "r"(id), "r"(cnt) : "memory")

// ---------------- K0: zero accumulators + pack Cw (parallel) --------------
__global__ void setup_kernel(const float* __restrict__ Cw) {
    if (blockIdx.x == 16) {
        for (int t = threadIdx.x; t < 4 * D_; t += 256) g_acc[t] = 0.0f;
        if (threadIdx.x == 0) g_done = 0u;
        return;
    }
    const int gid = blockIdx.x * 256 + threadIdx.x;   // 0..4095
    const int d = gid >> 5;
    const int t = gid & 31;
    const float4 v = reinterpret_cast<const float4*>(Cw)[gid];
    float hx = __bfloat162float(__float2bfloat16(v.x));
    float hy = __bfloat162float(__float2bfloat16(v.y));
    float hz = __bfloat162float(__float2bfloat16(v.z));
    float hw = __bfloat162float(__float2bfloat16(v.w));
    g_CwH[d * 64 + 2 * t + 0] = pack_bf(hx, hy);
    g_CwH[d * 64 + 2 * t + 1] = pack_bf(hz, hw);
    g_CwL[d * 64 + 2 * t + 0] = pack_bf(v.x - hx, v.y - hy);
    g_CwL[d * 64 + 2 * t + 1] = pack_bf(v.z - hz, v.w - hw);
}

// ---------------- K1: four projections  Xh = h @ Xw^T + Xb ----------------
__global__ void proj_kernel(const float* __restrict__ h,
                            const float* __restrict__ Uw, const float* __restrict__ Ub,
                            const float* __restrict__ Vw, const float* __restrict__ Vb,
                            const float* __restrict__ Aw, const float* __restrict__ Ab,
                            const float* __restrict__ Bw, const float* __restrict__ Bb) {
    extern __shared__ float sm[];
    float* hs = sm;              // 8*128
    float* wt = sm + 1024;       // 128*129
    const int tid = threadIdx.x;
    const int row0 = blockIdx.x * 8;

#pragma unroll
    for (int r = 0; r < 8; r++) hs[r * D_ + tid] = h[(row0 + r) * D_ + tid];

    const float* Ws[4] = {Uw, Vw, Aw, Bw};
    const float* bs[4] = {Ub, Vb, Ab, Bb};
    float* outs[4] = {g_Uh, g_Vh, g_Ah, g_Bh};

    for (int m = 0; m < 4; m++) {
        __syncthreads();
        const float4* W4 = reinterpret_cast<const float4*>(Ws[m]);
#pragma unroll
        for (int t = 0; t < 32; t++) {
            int idx4 = t * 128 + tid;
            float4 v = W4[idx4];
            int d = idx4 >> 5;
            int k = (idx4 & 31) << 2;
            wt[(k + 0) * 129 + d] = v.x;
            wt[(k + 1) * 129 + d] = v.y;
            wt[(k + 2) * 129 + d] = v.z;
            wt[(k + 3) * 129 + d] = v.w;
        }
        __syncthreads();

        float acc[8] = {0, 0, 0, 0, 0, 0, 0, 0};
        for (int k = 0; k < D_; k++) {
            float w = wt[k * 129 + tid];
#pragma unroll
            for (int r = 0; r < 8; r++) acc[r] += hs[r * D_ + k] * w;
        }
        float bias = bs[m][tid];
#pragma unroll
        for (int r = 0; r < 8; r++)
            outs[m][(row0 + r) * D_ + tid] = acc[r] + bias;
    }
}

// smem word-layout constants for fuse (warp-specialized, double-buffered)
#define E_STRIDE 68     // words per j-row of e tiles (64 + 4 pad)
#define CWL_STRIDE 68
#define XS_STRIDE 132
#define BUF_WORDS 8704                   // ehi(4352)+elo(4352) per buffer
#define CWL_OFF (2 * BUF_WORDS)          // 17408, 8704 words
#define RED_OFF (2 * BUF_WORDS + 8704)   // 26112, 384 floats
#define FUSE_WORDS (26112 + 384)         // 26496 words = 105984 B
// XS(p) (64x132 = 8448 floats) overlays buffer p (8704 words)

// ldmatrix-based mma over one j-tile. NT = number of 8-row j-groups (8 or 1).
template <int NT>
__device__ __forceinline__ void mma_tile(uint32_t cwl_s, uint32_t ehi_s, uint32_t elo_s,
                                         float acc[8][4], const uint32_t a_hi[8][4],
                                         uint32_t aw0, uint32_t bw0) {
#pragma unroll
    for (int ks = 0; ks < 8; ks++) {
        uint32_t al0, al1, al2, al3;
        ldmx4(al0, al1, al2, al3, cwl_s + (aw0 + 8 * ks) * 4);
#pragma unroll
        for (int nt2 = 0; nt2 < NT; nt2 += 2) {
            const uint32_t boff = (bw0 + nt2 * 8 * E_STRIDE + 8 * ks) * 4;
            uint32_t bh0a, bh1a, bh0b, bh1b, bl0a, bl1a, bl0b, bl1b;
            ldmx4(bh0a, bh1a, bh0b, bh1b, ehi_s + boff);
            ldmx4(bl0a, bl1a, bl0b, bl1b, elo_s + boff);
            mma16816(acc[nt2], a_hi[ks][0], a_hi[ks][1], a_hi[ks][2], a_hi[ks][3], bh0a, bh1a);
            mma16816(acc[nt2], al0, al1, al2, al3, bh0a, bh1a);
            mma16816(acc[nt2], a_hi[ks][0], a_hi[ks][1], a_hi[ks][2], a_hi[ks][3], bl0a, bl1a);
            if (NT > 1) {
                mma16816(acc[nt2 + 1], a_hi[ks][0], a_hi[ks][1], a_hi[ks][2], a_hi[ks][3], bh0b, bh1b);
                mma16816(acc[nt2 + 1], al0, al1, al2, al3, bh0b, bh1b);
                mma16816(acc[nt2 + 1], a_hi[ks][0], a_hi[ks][1], a_hi[ks][2], a_hi[ks][3], bl0b, bl1b);
            }
        }
    }
}

template <int NT>
__device__ __forceinline__ void spill_tile(float* __restrict__ XS, const float acc[8][4],
                                           int arow, int g, int tig) {
#pragma unroll
    for (int nt = 0; nt < NT; nt++) {
        const int jr = 8 * nt + 2 * tig;
        XS[jr * XS_STRIDE + arow] = acc[nt][0];
        XS[(jr + 1) * XS_STRIDE + arow] = acc[nt][1];
        XS[jr * XS_STRIDE + arow + 8] = acc[nt][2];
        XS[(jr + 1) * XS_STRIDE + arow + 8] = acc[nt][3];
    }
}

// ---------------- K2: warp-specialized fused kernel -----------------------
// grid = 1600 blocks (one per (b,i)), 384 threads.
// Warps 0-7 (tid<256): consumers (mma + spill + column + stats).
// Warps 8-11: producers (LDG e -> bf16 hi/lo split -> STS, double buffered).
// Named barriers: 1 = consumer-internal; 2+p = full[p]; 4+p = empty[p].
__global__ void __launch_bounds__(384, 1)
fuse_ws_kernel(const float* __restrict__ e,
               const float* __restrict__ Cb,
               const float* __restrict__ gamma_e, const float* __restrict__ beta_e,
               const float* __restrict__ gamma_h, const float* __restrict__ beta_h) {
    extern __shared__ uint32_t smw[];
    uint32_t* cwl = smw + CWL_OFF;
    float* red = reinterpret_cast<float*>(smw + RED_OFF);
    __shared__ unsigned int s_ticket;

    const int tid = threadIdx.x;
    const int lane = tid & 31;
    const int warp = tid >> 5;          // 0..11
    const bool is_cons = (tid < 256);
    const int bi = blockIdx.x;
    const int b = bi / N_;

    const float* e_base = e + (size_t)bi * N_ * D_;
    const uint32_t sbase = smem_u32(smw);
    const uint32_t cwl_s = sbase + CWL_OFF * 4;

    if (is_cons) {
        // ---- consumer setup: stage Cw-lo, zero red, load a_hi ----
        const int g = lane >> 2;
        const int tig = lane & 3;
        const int arow = warp * 16 + g;
        if (tid < 128) {
            red[tid] = 0.0f;
            red[128 + tid] = 0.0f;
            red[256 + tid] = 0.0f;
        }
        for (int w = tid; w < D_ * 64; w += 256) {
            cwl[(w >> 6) * CWL_STRIDE + (w & 63)] = g_CwL[w];
        }
        uint32_t a_hi[8][4];
#pragma unroll
        for (int ks = 0; ks < 8; ks++) {
            a_hi[ks][0] = g_CwH[arow * 64 + 8 * ks + tig];
            a_hi[ks][1] = g_CwH[(arow + 8) * 64 + 8 * ks + tig];
            a_hi[ks][2] = g_CwH[arow * 64 + 8 * ks + tig + 4];
            a_hi[ks][3] = g_CwH[(arow + 8) * 64 + 8 * ks + tig + 4];
        }
        BAR_SYNC(1, 256);   // cwl + red ready

        const int role = lane >> 3;
        const int rr = lane & 7;
        const uint32_t aw0 = (uint32_t)((warp * 16 + (role & 1) * 8 + rr) * CWL_STRIDE + (role >> 1) * 4);
        const uint32_t bw0 = (uint32_t)((8 * (role >> 1) + rr) * E_STRIDE + (role & 1) * 4);

        const int dcol = tid & 127;
        const int jh = tid >> 7;
        __half* xo_base = g_x + (size_t)bi * N_ * D_;
        const float* Ah_b = g_Ah + (size_t)b * N_ * D_;
        const float* Vh_b = g_Vh + (size_t)b * N_ * D_;
        const float Bh_r = g_Bh[(size_t)bi * D_ + dcol];
        const float Cb_r = Cb[dcol];

        float sumv = 0.0f, sqv = 0.0f, aggv = 0.0f;

        for (int t = 0; t < 4; t++) {
            const int p = t & 1;
            const int j0 = t * 64;
            const int jcnt = (t < 3) ? 64 : (N_ - 192);   // 64,64,64,8
            const uint32_t ehi_s = sbase + (p * BUF_WORDS) * 4;
            const uint32_t elo_s = sbase + (p * BUF_WORDS + 4352) * 4;
            float* XS = reinterpret_cast<float*>(smw + p * BUF_WORDS);

            BAR_SYNC(2 + p, 384);   // wait full[p]

            float acc[8][4];
#pragma unroll
            for (int nt = 0; nt < 8; nt++)
#pragma unroll
                for (int q = 0; q < 4; q++) acc[nt][q] = 0.0f;

            if (t < 3) {
                mma_tile<8>(cwl_s, ehi_s, elo_s, acc, a_hi, aw0, bw0);
            } else {
                mma_tile<1>(cwl_s, ehi_s, elo_s, acc, a_hi, aw0, bw0);
            }
            BAR_SYNC(1, 256);   // all consumer reads of buffer p done

            if (t < 3) {
                spill_tile<8>(XS, acc, arow, g, tig);
            } else {
                spill_tile<1>(XS, acc, arow, g, tig);
            }
            BAR_SYNC(1, 256);   // XS ready

            const int half = jcnt >> 1;
            if (half == 32) {
#pragma unroll
                for (int jj0 = 0; jj0 < 32; jj0 += 8) {
                    float xv[8], av[8], vv[8];
#pragma unroll
                    for (int u = 0; u < 8; u++) {
                        const int j = jh * 32 + jj0 + u;
                        xv[u] = XS[j * XS_STRIDE + dcol];
                        av[u] = Ah_b[(j0 + j) * D_ + dcol];
                        vv[u] = Vh_b[(j0 + j) * D_ + dcol];
                    }
#pragma unroll
                    for (int u = 0; u < 8; u++) {
                        const int j = jh * 32 + jj0 + u;
                        float x = xv[u] + Cb_r + Bh_r + av[u];
                        xo_base[(size_t)(j0 + j) * D_ + dcol] = __float2half_rn(x);
                        sumv += x;
                        sqv += x * x;
                        aggv += __fdividef(vv[u], 1.0f + __expf(-x));
                    }
                }
            } else {
                for (int jj = 0; jj < half; jj++) {
                    const int j = jh * half + jj;
                    float x = XS[j * XS_STRIDE + dcol] + Cb_r + Bh_r + Ah_b[(j0 + j) * D_ + dcol];
                    xo_base[(size_t)(j0 + j) * D_ + dcol] = __float2half_rn(x);
                    sumv += x;
                    sqv += x * x;
                    aggv += __fdividef(Vh_b[(j0 + j) * D_ + dcol], 1.0f + __expf(-x));
                }
            }
            if (t < 2) BAR_ARRIVE(4 + p, 384);   // buffer p free for tile t+2
        }

        // ---- per-pair reduction ----
        atomicAdd(&red[dcol], aggv);
        atomicAdd(&red[128 + dcol], sumv);
        atomicAdd(&red[256 + dcol], sqv);
    } else {
        // ---- producers: fill double-buffered bf16 tiles ----
        const int tp = tid - 256;   // 0..127
        for (int t = 0; t < 4; t++) {
            const int p = t & 1;
            if (t >= 2) BAR_SYNC(4 + p, 384);   // wait empty[p]
            const int jcnt = (t < 3) ? 64 : (N_ - 192);
            const int nf4 = jcnt * 32;
            const float4* E4 = reinterpret_cast<const float4*>(e_base) + t * 2048;
            uint32_t* e_hi = smw + p * BUF_WORDS;
            uint32_t* e_lo = smw + p * BUF_WORDS + 4352;
            for (int fid = tp; fid < nf4; fid += 128) {
                const int row = fid >> 5;
                const int k4 = fid & 31;
                float4 v = E4[fid];
                float hx = __bfloat162float(__float2bfloat16(v.x));
                float hy = __bfloat162float(__float2bfloat16(v.y));
                float hz = __bfloat162float(__float2bfloat16(v.z));
                float hw = __bfloat162float(__float2bfloat16(v.w));
                const int wofs = row * E_STRIDE + 2 * k4;
                *reinterpret_cast<uint2*>(&e_hi[wofs]) =
                    make_uint2(pack_bf(hx, hy), pack_bf(hz, hw));
                *reinterpret_cast<uint2*>(&e_lo[wofs]) =
                    make_uint2(pack_bf(v.x - hx, v.y - hy), pack_bf(v.z - hz, v.w - hw));
            }
            __threadfence_block();
            BAR_ARRIVE(2 + p, 384);   // full[p]
        }
    }

    __syncthreads();   // block-wide (384): red complete

    if (tid < 128) {
        const int d = tid;
        float hn = g_Uh[(size_t)bi * D_ + d] + red[d];
        g_hnew[(size_t)bi * D_ + d] = hn;
        atomicAdd(&g_acc[0 * D_ + d], red[128 + d]);
        atomicAdd(&g_acc[1 * D_ + d], red[256 + d]);
        atomicAdd(&g_acc[2 * D_ + d], hn);
        atomicAdd(&g_acc[3 * D_ + d], hn * hn);
    }

    // ---- last block computes BN coefficients (fused finalize) ----
    __threadfence();
    __syncthreads();
    if (tid == 0) s_ticket = atomicAdd(&g_done, 1u);
    __syncthreads();
    if (s_ticket == BN_ - 1 && tid < 128) {
        const int d = tid;
        const float Ne = (float)B_ * N_ * N_;
        float mu = g_acc[d] / Ne;
        float var = g_acc[D_ + d] / Ne - mu * mu;
        float sc = rsqrtf(var + EPS) * gamma_e[d];
        g_coef[d] = sc;
        g_coef[D_ + d] = beta_e[d] - mu * sc;

        const float Nh = (float)B_ * N_;
        float muh = g_acc[2 * D_ + d] / Nh;
        float varh = g_acc[3 * D_ + d] / Nh - muh * muh;
        float sch = rsqrtf(varh + EPS) * gamma_h[d];
        g_coef[2 * D_ + d] = sch;
        g_coef[3 * D_ + d] = beta_h[d] - muh * sch;
    }
}

// ---------------- K3: combined epilogue (e blocks then h blocks) ----------
__global__ void final_kernel(const float* __restrict__ e_in, const float* __restrict__ h_in,
                             float* __restrict__ e_out, float* __restrict__ h_out) {
    const int blk = blockIdx.x;
    if (blk < EBLKS) {
        size_t idx = (size_t)blk * 256 + threadIdx.x;   // float4 index
        int d4 = (int)(idx & 31);
        float4 sc = reinterpret_cast<const float4*>(g_coef)[d4];
        float4 sh = reinterpret_cast<const float4*>(g_coef + D_)[d4];
        uint2 xraw = *(reinterpret_cast<const uint2*>(g_x) + idx);
        __half2 xh0 = *reinterpret_cast<__half2*>(&xraw.x);
        __half2 xh1 = *reinterpret_cast<__half2*>(&xraw.y);
        float4 ei = reinterpret_cast<const float4*>(e_in)[idx];
        float4 r;
        r.x = ei.x + fmaxf(0.0f, __low2float(xh0) * sc.x + sh.x);
        r.y = ei.y + fmaxf(0.0f, __high2float(xh0) * sc.y + sh.y);
        r.z = ei.z + fmaxf(0.0f, __low2float(xh1) * sc.z + sh.z);
        r.w = ei.w + fmaxf(0.0f, __high2float(xh1) * sc.w + sh.w);
        reinterpret_cast<float4*>(e_out)[idx] = r;
    } else {
        size_t idx = (size_t)(blk - EBLKS) * 256 + threadIdx.x;
        int d4 = (int)(idx & 31);
        float4 sc = reinterpret_cast<const float4*>(g_coef + 2 * D_)[d4];
        float4 sh = reinterpret_cast<const float4*>(g_coef + 3 * D_)[d4];
        float4 x = reinterpret_cast<const float4*>(g_hnew)[idx];
        float4 hi = reinterpret_cast<const float4*>(h_in)[idx];
        float4 r;
        r.x = hi.x + fmaxf(0.0f, x.x * sc.x + sh.x);
        r.y = hi.y + fmaxf(0.0f, x.y * sc.y + sh.y);
        r.z = hi.z + fmaxf(0.0f, x.z * sc.z + sh.z);
        r.w = hi.w + fmaxf(0.0f, x.w * sc.w + sh.w);
        reinterpret_cast<float4*>(h_out)[idx] = r;
    }
}

// ---------------- launch ---------------------------------------------------
extern "C" void kernel_launch(void* const* d_in, const int* in_sizes, int n_in,
                              void* d_out, int out_size) {
    const float* h = (const float*)d_in[0];
    const float* e = (const float*)d_in[1];
    const float* Uw = (const float*)d_in[2];
    const float* Ub = (const float*)d_in[3];
    const float* Vw = (const float*)d_in[4];
    const float* Vb = (const float*)d_in[5];
    const float* Aw = (const float*)d_in[6];
    const float* Ab = (const float*)d_in[7];
    const float* Bw = (const float*)d_in[8];
    const float* Bb = (const float*)d_in[9];
    const float* Cw = (const float*)d_in[10];
    const float* Cb = (const float*)d_in[11];
    const float* gamma_h = (const float*)d_in[12];
    const float* beta_h = (const float*)d_in[13];
    const float* gamma_e = (const float*)d_in[14];
    const float* beta_e = (const float*)d_in[15];

    float* out = (float*)d_out;
    float* h_out = out;          // [B,N,D]
    float* e_out = out + HSZ;    // [B,N,N,D]

    static int attr_done = 0;
    const int proj_smem = (1024 + 16512) * 4;   // 70144 B
    const int fuse_smem = FUSE_WORDS * 4;       // 105984 B
    if (!attr_done) {
        cudaFuncSetAttribute(proj_kernel, cudaFuncAttributeMaxDynamicSharedMemorySize, proj_smem);
        cudaFuncSetAttribute(fuse_ws_kernel, cudaFuncAttributeMaxDynamicSharedMemorySize, fuse_smem);
        attr_done = 1;
    }

    setup_kernel<<<17, 256>>>(Cw);
    proj_kernel<<<BN_ / 8, 128, proj_smem>>>(h, Uw, Ub, Vw, Vb, Aw, Ab, Bw, Bb);
    fuse_ws_kernel<<<BN_, 384, fuse_smem>>>(e, Cb, gamma_e, beta_e, gamma_h, beta_h);
    final_kernel<<<EBLKS + HBLKS, 256>>>(e, h, e_out, h_out);
}

// round 15
// speedup vs baseline: 2.1618x; 2.1618x over previous
#include <cuda_runtime.h>
#include <cuda_bf16.h>
#include <cuda_fp16.h>
#include <cstdint>

#define B_ 8
#define N_ 200
#define D_ 128
#define BN_ (B_ * N_)            // 1600
#define HSZ (B_ * N_ * D_)       // 204800
#define ESZ (B_ * N_ * N_ * D_)  // 40960000
#define EPS 1e-5f
#define EBLKS (ESZ / 4 / 256)    // 40000
#define HBLKS (HSZ / 4 / 256)    // 200

// ---------------- scratch (device globals, no allocation) ----------------
__device__ float g_Uh[HSZ];
__device__ float g_Vh[HSZ];
__device__ float g_Ah[HSZ];
__device__ float g_Bh[HSZ];
__device__ float g_hnew[HSZ];
__device__ __align__(16) __half g_x[ESZ];   // fp16 e_new scratch (82 MB)
__device__ float g_acc[4 * D_];   // e_sum, e_sqsum, h_sum, h_sqsum
__device__ float g_coef[4 * D_];  // scale_e, shift_e, scale_h, shift_h
__device__ uint32_t g_CwT[D_ * D_];  // tf32-converted Cw, [d][k]
__device__ unsigned int g_done;

// ================= helpers ===========================================
__device__ __forceinline__ uint32_t to_tf32(float f) {
    uint32_t u;
    asm("cvt.rna.tf32.f32 %0, %1;" : "=r"(u) : "f"(f));
    return u;
}

__device__ __forceinline__ void mma1688_tf32(float* c,
                                             uint32_t a0, uint32_t a1, uint32_t a2, uint32_t a3,
                                             uint32_t b0, uint32_t b1) {
    asm volatile(
        "mma.sync.aligned.m16n8k8.row.col.f32.tf32.tf32.f32 "
        "{%0,%1,%2,%3}, {%4,%5,%6,%7}, {%8,%9}, {%0,%1,%2,%3};"
        : "+f"(c[0]), "+f"(c[1]), "+f"(c[2]), "+f"(c[3])
        : "r"(a0), "r"(a1), "r"(a2), "r"(a3), "r"(b0), "r"(b1));
}

__device__ __forceinline__ uint32_t smem_u32(const void* p) {
    uint32_t a;
    asm("{ .reg .u64 t; cvta.to.shared.u64 t, %1; cvt.u32.u64 %0, t; }" : "=r"(a) : "l"(p));
    return a;
}
#define CP_ASYNC16(dst, src) \
    asm volatile("cp.async.cg.shared.global [%0], [%1], 16;" :: "r"(dst), "l"(src))
#define CP_COMMIT() asm volatile("cp.async.commit_group;" ::: "memory")
#define CP_WAIT0() asm volatile("cp.async.wait_group 0;" ::: "memory")

// ---------------- K1: setup (blocks 200..216) + projections (0..199) ------
// grid = 217 blocks x 128 threads (proj part) / repurposed for setup.
__global__ void proj_setup_kernel(const float* __restrict__ h,
                                  const float* __restrict__ Uw, const float* __restrict__ Ub,
                                  const float* __restrict__ Vw, const float* __restrict__ Vb,
                                  const float* __restrict__ Aw, const float* __restrict__ Ab,
                                  const float* __restrict__ Bw, const float* __restrict__ Bb,
                                  const float* __restrict__ Cw) {
    const int blk = blockIdx.x;
    if (blk >= 200) {
        // ---- setup part: pack Cw to tf32 + zero accumulators ----
        if (blk == 216) {
            for (int t = threadIdx.x; t < 4 * D_; t += 128) g_acc[t] = 0.0f;
            if (threadIdx.x == 0) g_done = 0u;
            return;
        }
        // blocks 200..215: 16 blocks x 128 threads x 2 float4 = 4096 float4
        const int gid = (blk - 200) * 256 + threadIdx.x * 2;
#pragma unroll
        for (int s = 0; s < 2; s++) {
            const int g4 = gid + s;
            const int d = g4 >> 5;
            const int t = g4 & 31;
            const float4 v = reinterpret_cast<const float4*>(Cw)[g4];
            g_CwT[d * D_ + 4 * t + 0] = to_tf32(v.x);
            g_CwT[d * D_ + 4 * t + 1] = to_tf32(v.y);
            g_CwT[d * D_ + 4 * t + 2] = to_tf32(v.z);
            g_CwT[d * D_ + 4 * t + 3] = to_tf32(v.w);
        }
        return;
    }

    // ---- projection part ----
    extern __shared__ float sm[];
    float* hs = sm;              // 8*128
    float* wt = sm + 1024;       // 128*129
    const int tid = threadIdx.x;
    const int row0 = blk * 8;

#pragma unroll
    for (int r = 0; r < 8; r++) hs[r * D_ + tid] = h[(row0 + r) * D_ + tid];

    const float* Ws[4] = {Uw, Vw, Aw, Bw};
    const float* bs[4] = {Ub, Vb, Ab, Bb};
    float* outs[4] = {g_Uh, g_Vh, g_Ah, g_Bh};

    for (int m = 0; m < 4; m++) {
        __syncthreads();
        const float4* W4 = reinterpret_cast<const float4*>(Ws[m]);
#pragma unroll
        for (int t = 0; t < 32; t++) {
            int idx4 = t * 128 + tid;
            float4 v = W4[idx4];
            int d = idx4 >> 5;
            int k = (idx4 & 31) << 2;
            wt[(k + 0) * 129 + d] = v.x;
            wt[(k + 1) * 129 + d] = v.y;
            wt[(k + 2) * 129 + d] = v.z;
            wt[(k + 3) * 129 + d] = v.w;
        }
        __syncthreads();

        float acc[8] = {0, 0, 0, 0, 0, 0, 0, 0};
        for (int k = 0; k < D_; k++) {
            float w = wt[k * 129 + tid];
#pragma unroll
            for (int r = 0; r < 8; r++) acc[r] += hs[r * D_ + k] * w;
        }
        float bias = bs[m][tid];
#pragma unroll
        for (int r = 0; r < 8; r++)
            outs[m][(row0 + r) * D_ + tid] = acc[r] + bias;
    }
}

// smem layout for tf32 fuse: two fp32 e-tile buffers + red
#define EROW 132                         // floats per j-row (128 + 4 pad)
#define BUFW (64 * EROW)                 // 8448 words per buffer
#define RED_OFF (2 * BUFW)               // 16896
#define FUSE_WORDS (2 * BUFW + 384)      // 17280 words = 69120 B
#define XS_STRIDE EROW
// XS overlays the current buffer p

// tf32 single-pass mma over one j-tile. NT = 8 (64 rows) or 1 (8 rows).
template <int NT>
__device__ __forceinline__ void mma_tf32(const float* __restrict__ buf,
                                         float acc[8][4], const uint32_t a[16][4],
                                         int g, int tig) {
#pragma unroll
    for (int ks = 0; ks < 16; ks++) {
#pragma unroll
        for (int nt = 0; nt < NT; nt++) {
            const float* row = buf + (8 * nt + g) * EROW + 8 * ks + tig;
            uint32_t b0 = to_tf32(row[0]);
            uint32_t b1 = to_tf32(row[4]);
            mma1688_tf32(acc[nt], a[ks][0], a[ks][1], a[ks][2], a[ks][3], b0, b1);
        }
    }
}

template <int NT>
__device__ __forceinline__ void spill_tile(float* __restrict__ XS, const float acc[8][4],
                                           int arow, int g, int tig) {
#pragma unroll
    for (int nt = 0; nt < NT; nt++) {
        const int jr = 8 * nt + 2 * tig;
        XS[jr * XS_STRIDE + arow] = acc[nt][0];
        XS[(jr + 1) * XS_STRIDE + arow] = acc[nt][1];
        XS[jr * XS_STRIDE + arow + 8] = acc[nt][2];
        XS[(jr + 1) * XS_STRIDE + arow + 8] = acc[nt][3];
    }
}

// ---------------- K2: tf32 single-pass fused kernel -----------------------
// grid = 1600 blocks (one per (b,i)), 256 threads (8 warps).
// Ce[d,j] = sum_k Cw[d,k]*e[j,k]; A = Cw tf32 in regs, B = e fp32 in smem
// (cvt.rna in-loop). Double-buffered cp.async staging, no convert phase.
__global__ void __launch_bounds__(256, 2)
fuse_tf32_kernel(const float* __restrict__ e,
                 const float* __restrict__ Cb,
                 const float* __restrict__ gamma_e, const float* __restrict__ beta_e,
                 const float* __restrict__ gamma_h, const float* __restrict__ beta_h) {
    extern __shared__ float smf[];
    float* red = smf + RED_OFF;
    __shared__ unsigned int s_ticket;

    const int tid = threadIdx.x;
    const int lane = tid & 31;
    const int warp = tid >> 5;     // 0..7
    const int g = lane >> 2;
    const int tig = lane & 3;
    const int arow = warp * 16 + g;
    const int bi = blockIdx.x;
    const int b = bi / N_;
    const int dcol = tid & 127;
    const int jh = tid >> 7;       // 0 or 1

    const float* e_base = e + (size_t)bi * N_ * D_;
    const uint32_t sbase = smem_u32(smf);

    // ---- prologue: issue prefetch of tile 0 into buf0 ----
    {
        const float4* E4 = reinterpret_cast<const float4*>(e_base);
        for (int fid = tid; fid < 2048; fid += 256) {
            const int row = fid >> 5;
            const int k4 = fid & 31;
            CP_ASYNC16(sbase + (row * EROW + 4 * k4) * 4, (const char*)(E4 + fid));
        }
        CP_COMMIT();
    }

    if (tid < 128) {
        red[tid] = 0.0f;
        red[128 + tid] = 0.0f;
        red[256 + tid] = 0.0f;
    }

    // ---- A fragments: Cw tf32, 64 regs, loaded once (L2-hot) ----
    uint32_t a[16][4];
#pragma unroll
    for (int ks = 0; ks < 16; ks++) {
        a[ks][0] = g_CwT[arow * D_ + 8 * ks + tig];
        a[ks][1] = g_CwT[(arow + 8) * D_ + 8 * ks + tig];
        a[ks][2] = g_CwT[arow * D_ + 8 * ks + tig + 4];
        a[ks][3] = g_CwT[(arow + 8) * D_ + 8 * ks + tig + 4];
    }

    __half* xo_base = g_x + (size_t)bi * N_ * D_;
    const float* Ah_b = g_Ah + (size_t)b * N_ * D_;
    const float* Vh_b = g_Vh + (size_t)b * N_ * D_;
    const float Bh_r = g_Bh[(size_t)bi * D_ + dcol];
    const float Cb_r = Cb[dcol];

    float sumv = 0.0f, sqv = 0.0f, aggv = 0.0f;

    for (int t = 0; t < 4; t++) {
        const int p = t & 1;
        const int j0 = t * 64;
        const int jcnt = (t < 3) ? 64 : (N_ - 192);   // 64,64,64,8
        const float* buf = smf + p * BUFW;
        float* XS = smf + p * BUFW;

        CP_WAIT0();
        __syncthreads();   // buf p ready; all threads past column(t-1)

        // ---- issue prefetch(t+1) into buf p^1 (overlaps mma+spill+column) --
        if (t < 3) {
            const int njcnt = (t < 2) ? 64 : (N_ - 192);
            const int nnf4 = njcnt * 32;
            const float4* E4 = reinterpret_cast<const float4*>(e_base) + (t + 1) * 2048;
            const uint32_t dst0 = sbase + ((p ^ 1) * BUFW) * 4;
            for (int fid = tid; fid < nnf4; fid += 256) {
                const int row = fid >> 5;
                const int k4 = fid & 31;
                CP_ASYNC16(dst0 + (row * EROW + 4 * k4) * 4, (const char*)(E4 + fid));
            }
            CP_COMMIT();
        }

        // ---- mma (single tf32 pass) ----
        float acc[8][4];
#pragma unroll
        for (int nt = 0; nt < 8; nt++)
#pragma unroll
            for (int q = 0; q < 4; q++) acc[nt][q] = 0.0f;

        if (t < 3) {
            mma_tf32<8>(buf, acc, a, g, tig);
        } else {
            mma_tf32<1>(buf, acc, a, g, tig);
        }
        __syncthreads();   // mma reads of buf p done

        if (t < 3) {
            spill_tile<8>(XS, acc, arow, g, tig);
        } else {
            spill_tile<1>(XS, acc, arow, g, tig);
        }
        __syncthreads();   // XS ready

        // ---- column pass: thread (dcol, jh), batched prefetch ----
        const int half = jcnt >> 1;
        if (half == 32) {
#pragma unroll
            for (int jj0 = 0; jj0 < 32; jj0 += 8) {
                float xv[8], av[8], vv[8];
#pragma unroll
                for (int u = 0; u < 8; u++) {
                    const int j = jh * 32 + jj0 + u;
                    xv[u] = XS[j * XS_STRIDE + dcol];
                    av[u] = Ah_b[(j0 + j) * D_ + dcol];
                    vv[u] = Vh_b[(j0 + j) * D_ + dcol];
                }
#pragma unroll
                for (int u = 0; u < 8; u++) {
                    const int j = jh * 32 + jj0 + u;
                    float x = xv[u] + Cb_r + Bh_r + av[u];
                    xo_base[(size_t)(j0 + j) * D_ + dcol] = __float2half_rn(x);
                    sumv += x;
                    sqv += x * x;
                    aggv += __fdividef(vv[u], 1.0f + __expf(-x));
                }
            }
        } else {
            for (int jj = 0; jj < half; jj++) {
                const int j = jh * half + jj;
                float x = XS[j * XS_STRIDE + dcol] + Cb_r + Bh_r + Ah_b[(j0 + j) * D_ + dcol];
                xo_base[(size_t)(j0 + j) * D_ + dcol] = __float2half_rn(x);
                sumv += x;
                sqv += x * x;
                aggv += __fdividef(Vh_b[(j0 + j) * D_ + dcol], 1.0f + __expf(-x));
            }
        }
    }

    // ---- merge the two j-halves, then one global update per d ----
    __syncthreads();
    atomicAdd(&red[dcol], aggv);
    atomicAdd(&red[128 + dcol], sumv);
    atomicAdd(&red[256 + dcol], sqv);
    __syncthreads();

    if (tid < 128) {
        const int d = tid;
        float hn = g_Uh[(size_t)bi * D_ + d] + red[d];
        g_hnew[(size_t)bi * D_ + d] = hn;
        atomicAdd(&g_acc[0 * D_ + d], red[128 + d]);
        atomicAdd(&g_acc[1 * D_ + d], red[256 + d]);
        atomicAdd(&g_acc[2 * D_ + d], hn);
        atomicAdd(&g_acc[3 * D_ + d], hn * hn);
    }

    // ---- last block computes BN coefficients (fused finalize) ----
    __threadfence();
    __syncthreads();
    if (tid == 0) s_ticket = atomicAdd(&g_done, 1u);
    __syncthreads();
    if (s_ticket == BN_ - 1 && tid < 128) {
        const int d = tid;
        const float Ne = (float)B_ * N_ * N_;
        float mu = g_acc[d] / Ne;
        float var = g_acc[D_ + d] / Ne - mu * mu;
        float sc = rsqrtf(var + EPS) * gamma_e[d];
        g_coef[d] = sc;
        g_coef[D_ + d] = beta_e[d] - mu * sc;

        const float Nh = (float)B_ * N_;
        float muh = g_acc[2 * D_ + d] / Nh;
        float varh = g_acc[3 * D_ + d] / Nh - muh * muh;
        float sch = rsqrtf(varh + EPS) * gamma_h[d];
        g_coef[2 * D_ + d] = sch;
        g_coef[3 * D_ + d] = beta_h[d] - muh * sch;
    }
}

// ---------------- K3: combined epilogue (e blocks then h blocks) ----------
__global__ void final_kernel(const float* __restrict__ e_in, const float* __restrict__ h_in,
                             float* __restrict__ e_out, float* __restrict__ h_out) {
    const int blk = blockIdx.x;
    if (blk < EBLKS) {
        size_t idx = (size_t)blk * 256 + threadIdx.x;   // float4 index
        int d4 = (int)(idx & 31);
        float4 sc = reinterpret_cast<const float4*>(g_coef)[d4];
        float4 sh = reinterpret_cast<const float4*>(g_coef + D_)[d4];
        uint2 xraw = *(reinterpret_cast<const uint2*>(g_x) + idx);
        __half2 xh0 = *reinterpret_cast<__half2*>(&xraw.x);
        __half2 xh1 = *reinterpret_cast<__half2*>(&xraw.y);
        float4 ei = reinterpret_cast<const float4*>(e_in)[idx];
        float4 r;
        r.x = ei.x + fmaxf(0.0f, __low2float(xh0) * sc.x + sh.x);
        r.y = ei.y + fmaxf(0.0f, __high2float(xh0) * sc.y + sh.y);
        r.z = ei.z + fmaxf(0.0f, __low2float(xh1) * sc.z + sh.z);
        r.w = ei.w + fmaxf(0.0f, __high2float(xh1) * sc.w + sh.w);
        reinterpret_cast<float4*>(e_out)[idx] = r;
    } else {
        size_t idx = (size_t)(blk - EBLKS) * 256 + threadIdx.x;
        int d4 = (int)(idx & 31);
        float4 sc = reinterpret_cast<const float4*>(g_coef + 2 * D_)[d4];
        float4 sh = reinterpret_cast<const float4*>(g_coef + 3 * D_)[d4];
        float4 x = reinterpret_cast<const float4*>(g_hnew)[idx];
        float4 hi = reinterpret_cast<const float4*>(h_in)[idx];
        float4 r;
        r.x = hi.x + fmaxf(0.0f, x.x * sc.x + sh.x);
        r.y = hi.y + fmaxf(0.0f, x.y * sc.y + sh.y);
        r.z = hi.z + fmaxf(0.0f, x.z * sc.z + sh.z);
        r.w = hi.w + fmaxf(0.0f, x.w * sc.w + sh.w);
        reinterpret_cast<float4*>(h_out)[idx] = r;
    }
}

// ---------------- launch ---------------------------------------------------
extern "C" void kernel_launch(void* const* d_in, const int* in_sizes, int n_in,
                              void* d_out, int out_size) {
    const float* h = (const float*)d_in[0];
    const float* e = (const float*)d_in[1];
    const float* Uw = (const float*)d_in[2];
    const float* Ub = (const float*)d_in[3];
    const float* Vw = (const float*)d_in[4];
    const float* Vb = (const float*)d_in[5];
    const float* Aw = (const float*)d_in[6];
    const float* Ab = (const float*)d_in[7];
    const float* Bw = (const float*)d_in[8];
    const float* Bb = (const float*)d_in[9];
    const float* Cw = (const float*)d_in[10];
    const float* Cb = (const float*)d_in[11];
    const float* gamma_h = (const float*)d_in[12];
    const float* beta_h = (const float*)d_in[13];
    const float* gamma_e = (const float*)d_in[14];
    const float* beta_e = (const float*)d_in[15];

    float* out = (float*)d_out;
    float* h_out = out;          // [B,N,D]
    float* e_out = out + HSZ;    // [B,N,N,D]

    static int attr_done = 0;
    const int proj_smem = (1024 + 16512) * 4;   // 70144 B
    const int fuse_smem = FUSE_WORDS * 4;       // 69120 B
    if (!attr_done) {
        cudaFuncSetAttribute(proj_setup_kernel, cudaFuncAttributeMaxDynamicSharedMemorySize, proj_smem);
        cudaFuncSetAttribute(fuse_tf32_kernel, cudaFuncAttributeMaxDynamicSharedMemorySize, fuse_smem);
        attr_done = 1;
    }

    proj_setup_kernel<<<217, 128, proj_smem>>>(h, Uw, Ub, Vw, Vb, Aw, Ab, Bw, Bb, Cw);
    fuse_tf32_kernel<<<BN_, 256, fuse_smem>>>(e, Cb, gamma_e, beta_e, gamma_h, beta_h);
    final_kernel<<<EBLKS + HBLKS, 256>>>(e, h, e_out, h_out);
}

// round 16
// speedup vs baseline: 2.4511x; 1.1338x over previous
#include <cuda_runtime.h>
#include <cuda_bf16.h>
#include <cuda_fp16.h>
#include <cstdint>

#define B_ 8
#define N_ 200
#define D_ 128
#define BN_ (B_ * N_)            // 1600
#define HSZ (B_ * N_ * D_)       // 204800
#define ESZ (B_ * N_ * N_ * D_)  // 40960000
#define EPS 1e-5f
#define EBLKS (ESZ / 4 / 256)    // 40000
#define HBLKS (HSZ / 4 / 256)    // 200

// ---------------- scratch (device globals, no allocation) ----------------
__device__ float g_Uh[HSZ];
__device__ float g_Vh[HSZ];
__device__ float g_Ah[HSZ];
__device__ float g_Bh[HSZ];
__device__ float g_hnew[HSZ];
__device__ __align__(16) __half g_x[ESZ];   // fp16 e_new scratch (82 MB)
__device__ float g_acc[4 * D_];   // e_sum, e_sqsum, h_sum, h_sqsum
__device__ float g_coef[4 * D_];  // scale_e, shift_e, scale_h, shift_h
__device__ uint32_t g_CwT[D_ * D_];  // tf32-converted Cw, [d][k]
__device__ unsigned int g_done;

// ================= helpers ===========================================
__device__ __forceinline__ uint32_t to_tf32(float f) {
    uint32_t u;
    asm("cvt.rna.tf32.f32 %0, %1;" : "=r"(u) : "f"(f));
    return u;
}

__device__ __forceinline__ void mma1688_tf32(float* c,
                                             uint32_t a0, uint32_t a1, uint32_t a2, uint32_t a3,
                                             uint32_t b0, uint32_t b1) {
    asm volatile(
        "mma.sync.aligned.m16n8k8.row.col.f32.tf32.tf32.f32 "
        "{%0,%1,%2,%3}, {%4,%5,%6,%7}, {%8,%9}, {%0,%1,%2,%3};"
        : "+f"(c[0]), "+f"(c[1]), "+f"(c[2]), "+f"(c[3])
        : "r"(a0), "r"(a1), "r"(a2), "r"(a3), "r"(b0), "r"(b1));
}

__device__ __forceinline__ uint32_t smem_u32(const void* p) {
    uint32_t a;
    asm("{ .reg .u64 t; cvta.to.shared.u64 t, %1; cvt.u32.u64 %0, t; }" : "=r"(a) : "l"(p));
    return a;
}
#define CP_ASYNC16(dst, src) \
    asm volatile("cp.async.cg.shared.global [%0], [%1], 16;" :: "r"(dst), "l"(src))
#define CP_COMMIT() asm volatile("cp.async.commit_group;" ::: "memory")
#define CP_WAIT0() asm volatile("cp.async.wait_group 0;" ::: "memory")

// ---------------- K1: projections (0..799) + setup (800..816) -------------
// proj: grid-split over (matrix m, row-group). block = 128 threads.
__global__ void proj_setup_kernel(const float* __restrict__ h,
                                  const float* __restrict__ Uw, const float* __restrict__ Ub,
                                  const float* __restrict__ Vw, const float* __restrict__ Vb,
                                  const float* __restrict__ Aw, const float* __restrict__ Ab,
                                  const float* __restrict__ Bw, const float* __restrict__ Bb,
                                  const float* __restrict__ Cw) {
    const int blk = blockIdx.x;
    if (blk >= 800) {
        // ---- setup part: pack Cw to tf32 + zero accumulators ----
        if (blk == 816) {
            for (int t = threadIdx.x; t < 4 * D_; t += 128) g_acc[t] = 0.0f;
            if (threadIdx.x == 0) g_done = 0u;
            return;
        }
        // blocks 800..815: 16 blocks x 128 threads x 2 float4 = 4096 float4
        const int gid = (blk - 800) * 256 + threadIdx.x * 2;
#pragma unroll
        for (int s = 0; s < 2; s++) {
            const int g4 = gid + s;
            const int d = g4 >> 5;
            const int t = g4 & 31;
            const float4 v = reinterpret_cast<const float4*>(Cw)[g4];
            g_CwT[d * D_ + 4 * t + 0] = to_tf32(v.x);
            g_CwT[d * D_ + 4 * t + 1] = to_tf32(v.y);
            g_CwT[d * D_ + 4 * t + 2] = to_tf32(v.z);
            g_CwT[d * D_ + 4 * t + 3] = to_tf32(v.w);
        }
        return;
    }

    // ---- projection part: one matrix, 8 rows per block ----
    extern __shared__ float sm[];
    float* hs = sm;              // 8*128
    float* wt = sm + 1024;       // 128*129
    const int tid = threadIdx.x;
    const int m = blk & 3;
    const int row0 = (blk >> 2) * 8;

    const float* Ws[4] = {Uw, Vw, Aw, Bw};
    const float* bs[4] = {Ub, Vb, Ab, Bb};
    float* outs[4] = {g_Uh, g_Vh, g_Ah, g_Bh};

#pragma unroll
    for (int r = 0; r < 8; r++) hs[r * D_ + tid] = h[(row0 + r) * D_ + tid];

    // load W_m transposed into wt[k][d] (padded stride 129)
    {
        const float4* W4 = reinterpret_cast<const float4*>(Ws[m]);
#pragma unroll
        for (int t = 0; t < 32; t++) {
            int idx4 = t * 128 + tid;
            float4 v = W4[idx4];
            int d = idx4 >> 5;
            int k = (idx4 & 31) << 2;
            wt[(k + 0) * 129 + d] = v.x;
            wt[(k + 1) * 129 + d] = v.y;
            wt[(k + 2) * 129 + d] = v.z;
            wt[(k + 3) * 129 + d] = v.w;
        }
    }
    __syncthreads();

    float acc[8] = {0, 0, 0, 0, 0, 0, 0, 0};
    for (int k = 0; k < D_; k++) {
        float w = wt[k * 129 + tid];
#pragma unroll
        for (int r = 0; r < 8; r++) acc[r] += hs[r * D_ + k] * w;
    }
    float bias = bs[m][tid];
#pragma unroll
    for (int r = 0; r < 8; r++)
        outs[m][(row0 + r) * D_ + tid] = acc[r] + bias;
}

// smem layout for tf32 fuse: two fp32 e-tile buffers + red
#define EROW 132                         // floats per j-row (128 + 4 pad)
#define BUFW (64 * EROW)                 // 8448 words per buffer
#define RED_OFF (2 * BUFW)               // 16896
#define FUSE_WORDS (2 * BUFW + 384)      // 17280 words = 69120 B
#define XS_STRIDE EROW
// XS overlays the current buffer p

// tf32 single-pass mma over one j-tile. NT = 8 (64 rows) or 1 (8 rows).
template <int NT>
__device__ __forceinline__ void mma_tf32(const float* __restrict__ buf,
                                         float acc[8][4], const uint32_t a[16][4],
                                         int g, int tig) {
#pragma unroll
    for (int ks = 0; ks < 16; ks++) {
#pragma unroll
        for (int nt = 0; nt < NT; nt++) {
            const float* row = buf + (8 * nt + g) * EROW + 8 * ks + tig;
            uint32_t b0 = to_tf32(row[0]);
            uint32_t b1 = to_tf32(row[4]);
            mma1688_tf32(acc[nt], a[ks][0], a[ks][1], a[ks][2], a[ks][3], b0, b1);
        }
    }
}

template <int NT>
__device__ __forceinline__ void spill_tile(float* __restrict__ XS, const float acc[8][4],
                                           int arow, int g, int tig) {
#pragma unroll
    for (int nt = 0; nt < NT; nt++) {
        const int jr = 8 * nt + 2 * tig;
        XS[jr * XS_STRIDE + arow] = acc[nt][0];
        XS[(jr + 1) * XS_STRIDE + arow] = acc[nt][1];
        XS[jr * XS_STRIDE + arow + 8] = acc[nt][2];
        XS[(jr + 1) * XS_STRIDE + arow + 8] = acc[nt][3];
    }
}

// ---------------- K2: tf32 single-pass fused kernel -----------------------
// grid = 1600 blocks (one per (b,i)), 256 threads (8 warps).
__global__ void __launch_bounds__(256, 2)
fuse_tf32_kernel(const float* __restrict__ e,
                 const float* __restrict__ Cb,
                 const float* __restrict__ gamma_e, const float* __restrict__ beta_e,
                 const float* __restrict__ gamma_h, const float* __restrict__ beta_h) {
    extern __shared__ float smf[];
    float* red = smf + RED_OFF;
    __shared__ unsigned int s_ticket;

    const int tid = threadIdx.x;
    const int lane = tid & 31;
    const int warp = tid >> 5;     // 0..7
    const int g = lane >> 2;
    const int tig = lane & 3;
    const int arow = warp * 16 + g;
    const int bi = blockIdx.x;
    const int b = bi / N_;
    const int dcol = tid & 127;
    const int jh = tid >> 7;       // 0 or 1

    const float* e_base = e + (size_t)bi * N_ * D_;
    const uint32_t sbase = smem_u32(smf);

    // ---- prologue: issue prefetch of tile 0 into buf0 ----
    {
        const float4* E4 = reinterpret_cast<const float4*>(e_base);
        for (int fid = tid; fid < 2048; fid += 256) {
            const int row = fid >> 5;
            const int k4 = fid & 31;
            CP_ASYNC16(sbase + (row * EROW + 4 * k4) * 4, (const char*)(E4 + fid));
        }
        CP_COMMIT();
    }

    if (tid < 128) {
        red[tid] = 0.0f;
        red[128 + tid] = 0.0f;
        red[256 + tid] = 0.0f;
    }

    // ---- A fragments: Cw tf32, 64 regs, loaded once (L2-hot) ----
    uint32_t a[16][4];
#pragma unroll
    for (int ks = 0; ks < 16; ks++) {
        a[ks][0] = g_CwT[arow * D_ + 8 * ks + tig];
        a[ks][1] = g_CwT[(arow + 8) * D_ + 8 * ks + tig];
        a[ks][2] = g_CwT[arow * D_ + 8 * ks + tig + 4];
        a[ks][3] = g_CwT[(arow + 8) * D_ + 8 * ks + tig + 4];
    }

    __half* xo_base = g_x + (size_t)bi * N_ * D_;
    const float* Ah_b = g_Ah + (size_t)b * N_ * D_;
    const float* Vh_b = g_Vh + (size_t)b * N_ * D_;
    const float Bh_r = g_Bh[(size_t)bi * D_ + dcol];
    const float Cb_r = Cb[dcol];

    float sumv = 0.0f, sqv = 0.0f, aggv = 0.0f;

    for (int t = 0; t < 4; t++) {
        const int p = t & 1;
        const int j0 = t * 64;
        const int jcnt = (t < 3) ? 64 : (N_ - 192);   // 64,64,64,8
        const float* buf = smf + p * BUFW;
        float* XS = smf + p * BUFW;

        CP_WAIT0();
        __syncthreads();   // buf p ready; all threads past column(t-1)

        // ---- issue prefetch(t+1) into buf p^1 (overlaps mma+spill+column) --
        if (t < 3) {
            const int njcnt = (t < 2) ? 64 : (N_ - 192);
            const int nnf4 = njcnt * 32;
            const float4* E4 = reinterpret_cast<const float4*>(e_base) + (t + 1) * 2048;
            const uint32_t dst0 = sbase + ((p ^ 1) * BUFW) * 4;
            for (int fid = tid; fid < nnf4; fid += 256) {
                const int row = fid >> 5;
                const int k4 = fid & 31;
                CP_ASYNC16(dst0 + (row * EROW + 4 * k4) * 4, (const char*)(E4 + fid));
            }
            CP_COMMIT();
        }

        // ---- mma (single tf32 pass) ----
        float acc[8][4];
#pragma unroll
        for (int nt = 0; nt < 8; nt++)
#pragma unroll
            for (int q = 0; q < 4; q++) acc[nt][q] = 0.0f;

        if (t < 3) {
            mma_tf32<8>(buf, acc, a, g, tig);
        } else {
            mma_tf32<1>(buf, acc, a, g, tig);
        }
        __syncthreads();   // mma reads of buf p done

        if (t < 3) {
            spill_tile<8>(XS, acc, arow, g, tig);
        } else {
            spill_tile<1>(XS, acc, arow, g, tig);
        }
        __syncthreads();   // XS ready

        // ---- column pass: thread (dcol, jh), batched prefetch ----
        const int half = jcnt >> 1;
        if (half == 32) {
#pragma unroll
            for (int jj0 = 0; jj0 < 32; jj0 += 8) {
                float xv[8], av[8], vv[8];
#pragma unroll
                for (int u = 0; u < 8; u++) {
                    const int j = jh * 32 + jj0 + u;
                    xv[u] = XS[j * XS_STRIDE + dcol];
                    av[u] = Ah_b[(j0 + j) * D_ + dcol];
                    vv[u] = Vh_b[(j0 + j) * D_ + dcol];
                }
#pragma unroll
                for (int u = 0; u < 8; u++) {
                    const int j = jh * 32 + jj0 + u;
                    float x = xv[u] + Cb_r + Bh_r + av[u];
                    xo_base[(size_t)(j0 + j) * D_ + dcol] = __float2half_rn(x);
                    sumv += x;
                    sqv += x * x;
                    aggv += __fdividef(vv[u], 1.0f + __expf(-x));
                }
            }
        } else {
            for (int jj = 0; jj < half; jj++) {
                const int j = jh * half + jj;
                float x = XS[j * XS_STRIDE + dcol] + Cb_r + Bh_r + Ah_b[(j0 + j) * D_ + dcol];
                xo_base[(size_t)(j0 + j) * D_ + dcol] = __float2half_rn(x);
                sumv += x;
                sqv += x * x;
                aggv += __fdividef(Vh_b[(j0 + j) * D_ + dcol], 1.0f + __expf(-x));
            }
        }
    }

    // ---- merge the two j-halves, then one global update per d ----
    __syncthreads();
    atomicAdd(&red[dcol], aggv);
    atomicAdd(&red[128 + dcol], sumv);
    atomicAdd(&red[256 + dcol], sqv);
    __syncthreads();

    if (tid < 128) {
        const int d = tid;
        float hn = g_Uh[(size_t)bi * D_ + d] + red[d];
        g_hnew[(size_t)bi * D_ + d] = hn;
        atomicAdd(&g_acc[0 * D_ + d], red[128 + d]);
        atomicAdd(&g_acc[1 * D_ + d], red[256 + d]);
        atomicAdd(&g_acc[2 * D_ + d], hn);
        atomicAdd(&g_acc[3 * D_ + d], hn * hn);
    }

    // ---- last block computes BN coefficients (fused finalize) ----
    __threadfence();
    __syncthreads();
    if (tid == 0) s_ticket = atomicAdd(&g_done, 1u);
    __syncthreads();
    if (s_ticket == BN_ - 1 && tid < 128) {
        const int d = tid;
        const float Ne = (float)B_ * N_ * N_;
        float mu = g_acc[d] / Ne;
        float var = g_acc[D_ + d] / Ne - mu * mu;
        float sc = rsqrtf(var + EPS) * gamma_e[d];
        g_coef[d] = sc;
        g_coef[D_ + d] = beta_e[d] - mu * sc;

        const float Nh = (float)B_ * N_;
        float muh = g_acc[2 * D_ + d] / Nh;
        float varh = g_acc[3 * D_ + d] / Nh - muh * muh;
        float sch = rsqrtf(varh + EPS) * gamma_h[d];
        g_coef[2 * D_ + d] = sch;
        g_coef[3 * D_ + d] = beta_h[d] - muh * sch;
    }
}

// ---------------- K3: combined epilogue (e blocks then h blocks) ----------
__global__ void final_kernel(const float* __restrict__ e_in, const float* __restrict__ h_in,
                             float* __restrict__ e_out, float* __restrict__ h_out) {
    const int blk = blockIdx.x;
    if (blk < EBLKS) {
        size_t idx = (size_t)blk * 256 + threadIdx.x;   // float4 index
        int d4 = (int)(idx & 31);
        float4 sc = reinterpret_cast<const float4*>(g_coef)[d4];
        float4 sh = reinterpret_cast<const float4*>(g_coef + D_)[d4];
        uint2 xraw = *(reinterpret_cast<const uint2*>(g_x) + idx);
        __half2 xh0 = *reinterpret_cast<__half2*>(&xraw.x);
        __half2 xh1 = *reinterpret_cast<__half2*>(&xraw.y);
        float4 ei = reinterpret_cast<const float4*>(e_in)[idx];
        float4 r;
        r.x = ei.x + fmaxf(0.0f, __low2float(xh0) * sc.x + sh.x);
        r.y = ei.y + fmaxf(0.0f, __high2float(xh0) * sc.y + sh.y);
        r.z = ei.z + fmaxf(0.0f, __low2float(xh1) * sc.z + sh.z);
        r.w = ei.w + fmaxf(0.0f, __high2float(xh1) * sc.w + sh.w);
        reinterpret_cast<float4*>(e_out)[idx] = r;
    } else {
        size_t idx = (size_t)(blk - EBLKS) * 256 + threadIdx.x;
        int d4 = (int)(idx & 31);
        float4 sc = reinterpret_cast<const float4*>(g_coef + 2 * D_)[d4];
        float4 sh = reinterpret_cast<const float4*>(g_coef + 3 * D_)[d4];
        float4 x = reinterpret_cast<const float4*>(g_hnew)[idx];
        float4 hi = reinterpret_cast<const float4*>(h_in)[idx];
        float4 r;
        r.x = hi.x + fmaxf(0.0f, x.x * sc.x + sh.x);
        r.y = hi.y + fmaxf(0.0f, x.y * sc.y + sh.y);
        r.z = hi.z + fmaxf(0.0f, x.z * sc.z + sh.z);
        r.w = hi.w + fmaxf(0.0f, x.w * sc.w + sh.w);
        reinterpret_cast<float4*>(h_out)[idx] = r;
    }
}

// ---------------- launch ---------------------------------------------------
extern "C" void kernel_launch(void* const* d_in, const int* in_sizes, int n_in,
                              void* d_out, int out_size) {
    const float* h = (const float*)d_in[0];
    const float* e = (const float*)d_in[1];
    const float* Uw = (const float*)d_in[2];
    const float* Ub = (const float*)d_in[3];
    const float* Vw = (const float*)d_in[4];
    const float* Vb = (const float*)d_in[5];
    const float* Aw = (const float*)d_in[6];
    const float* Ab = (const float*)d_in[7];
    const float* Bw = (const float*)d_in[8];
    const float* Bb = (const float*)d_in[9];
    const float* Cw = (const float*)d_in[10];
    const float* Cb = (const float*)d_in[11];
    const float* gamma_h = (const float*)d_in[12];
    const float* beta_h = (const float*)d_in[13];
    const float* gamma_e = (const float*)d_in[14];
    const float* beta_e = (const float*)d_in[15];

    float* out = (float*)d_out;
    float* h_out = out;          // [B,N,D]
    float* e_out = out + HSZ;    // [B,N,N,D]

    static int attr_done = 0;
    const int proj_smem = (1024 + 16512) * 4;   // 70144 B
    const int fuse_smem = FUSE_WORDS * 4;       // 69120 B
    if (!attr_done) {
        cudaFuncSetAttribute(proj_setup_kernel, cudaFuncAttributeMaxDynamicSharedMemorySize, proj_smem);
        cudaFuncSetAttribute(fuse_tf32_kernel, cudaFuncAttributeMaxDynamicSharedMemorySize, fuse_smem);
        attr_done = 1;
    }

    proj_setup_kernel<<<817, 128, proj_smem>>>(h, Uw, Ub, Vw, Vb, Aw, Ab, Bw, Bb, Cw);
    fuse_tf32_kernel<<<BN_, 256, fuse_smem>>>(e, Cb, gamma_e, beta_e, gamma_h, beta_h);
    final_kernel<<<EBLKS + HBLKS, 256>>>(e, h, e_out, h_out);
}

// round 17
// speedup vs baseline: 2.5627x; 1.0455x over previous
#include <cuda_runtime.h>
#include <cuda_bf16.h>
#include <cuda_fp16.h>
#include <cstdint>

#define B_ 8
#define N_ 200
#define D_ 128
#define BN_ (B_ * N_)            // 1600
#define HSZ (B_ * N_ * D_)       // 204800
#define ESZ (B_ * N_ * N_ * D_)  // 40960000
#define EPS 1e-5f
#define EBLKS (ESZ / 4 / 256)    // 40000
#define HBLKS (HSZ / 4 / 256)    // 200

// ---------------- scratch (device globals, no allocation) ----------------
__device__ float g_Uh[HSZ];
__device__ float g_Vh[HSZ];
__device__ float g_Ah[HSZ];
__device__ float g_Bh[HSZ];
__device__ float g_hnew[HSZ];
__device__ __align__(16) __half g_x[ESZ];   // fp16 e_new scratch (82 MB)
__device__ float g_acc[4 * D_];   // e_sum, e_sqsum, h_sum, h_sqsum
__device__ float g_coef[4 * D_];  // scale_e, shift_e, scale_h, shift_h
__device__ uint32_t g_CwT[D_ * D_];  // tf32-converted Cw, [d][k]
__device__ unsigned int g_done;

// ================= helpers ===========================================
__device__ __forceinline__ uint32_t to_tf32(float f) {
    uint32_t u;
    asm("cvt.rna.tf32.f32 %0, %1;" : "=r"(u) : "f"(f));
    return u;
}

__device__ __forceinline__ void mma1688_tf32(float* c,
                                             uint32_t a0, uint32_t a1, uint32_t a2, uint32_t a3,
                                             uint32_t b0, uint32_t b1) {
    asm volatile(
        "mma.sync.aligned.m16n8k8.row.col.f32.tf32.tf32.f32 "
        "{%0,%1,%2,%3}, {%4,%5,%6,%7}, {%8,%9}, {%0,%1,%2,%3};"
        : "+f"(c[0]), "+f"(c[1]), "+f"(c[2]), "+f"(c[3])
        : "r"(a0), "r"(a1), "r"(a2), "r"(a3), "r"(b0), "r"(b1));
}

__device__ __forceinline__ uint32_t smem_u32(const void* p) {
    uint32_t a;
    asm("{ .reg .u64 t; cvta.to.shared.u64 t, %1; cvt.u32.u64 %0, t; }" : "=r"(a) : "l"(p));
    return a;
}
#define CP_ASYNC16(dst, src) \
    asm volatile("cp.async.cg.shared.global [%0], [%1], 16;" :: "r"(dst), "l"(src))
#define CP_COMMIT() asm volatile("cp.async.commit_group;" ::: "memory")
#define CP_WAIT0() asm volatile("cp.async.wait_group 0;" ::: "memory")

// ---------------- K1: projections (0..799) + setup (800..816) -------------
// proj: block = (matrix m, 8 rows). Thread = output channel d.
// W row held in registers (16-k chunks); h rows broadcast from smem via LDS.128.
__global__ void __launch_bounds__(128) proj_setup_kernel(
        const float* __restrict__ h,
        const float* __restrict__ Uw, const float* __restrict__ Ub,
        const float* __restrict__ Vw, const float* __restrict__ Vb,
        const float* __restrict__ Aw, const float* __restrict__ Ab,
        const float* __restrict__ Bw, const float* __restrict__ Bb,
        const float* __restrict__ Cw) {
    const int blk = blockIdx.x;
    if (blk >= 800) {
        // ---- setup part: pack Cw to tf32 + zero accumulators ----
        if (blk == 816) {
            for (int t = threadIdx.x; t < 4 * D_; t += 128) g_acc[t] = 0.0f;
            if (threadIdx.x == 0) g_done = 0u;
            return;
        }
        const int gid = (blk - 800) * 256 + threadIdx.x * 2;
#pragma unroll
        for (int s = 0; s < 2; s++) {
            const int g4 = gid + s;
            const int d = g4 >> 5;
            const int t = g4 & 31;
            const float4 v = reinterpret_cast<const float4*>(Cw)[g4];
            g_CwT[d * D_ + 4 * t + 0] = to_tf32(v.x);
            g_CwT[d * D_ + 4 * t + 1] = to_tf32(v.y);
            g_CwT[d * D_ + 4 * t + 2] = to_tf32(v.z);
            g_CwT[d * D_ + 4 * t + 3] = to_tf32(v.w);
        }
        return;
    }

    // ---- projection part: one matrix, 8 rows ----
    __shared__ __align__(16) float hs[8 * D_];   // 4 KB
    const int tid = threadIdx.x;                 // = output channel d
    const int m = blk & 3;
    const int row0 = (blk >> 2) * 8;

    const float* Ws[4] = {Uw, Vw, Aw, Bw};
    const float* bs[4] = {Ub, Vb, Ab, Bb};
    float* outs[4] = {g_Uh, g_Vh, g_Ah, g_Bh};

#pragma unroll
    for (int r = 0; r < 8; r++) hs[r * D_ + tid] = h[(row0 + r) * D_ + tid];
    __syncthreads();

    const float4* Wrow = reinterpret_cast<const float4*>(Ws[m] + (size_t)tid * D_);
    float acc[8] = {0, 0, 0, 0, 0, 0, 0, 0};

#pragma unroll
    for (int c = 0; c < 8; c++) {          // k-chunks of 16
        float4 w4[4];
#pragma unroll
        for (int q = 0; q < 4; q++) w4[q] = Wrow[c * 4 + q];
#pragma unroll
        for (int q = 0; q < 4; q++) {
            const int k = c * 16 + q * 4;
#pragma unroll
            for (int r = 0; r < 8; r++) {
                float4 hv = *reinterpret_cast<const float4*>(&hs[r * D_ + k]);
                acc[r] += hv.x * w4[q].x + hv.y * w4[q].y + hv.z * w4[q].z + hv.w * w4[q].w;
            }
        }
    }
    const float bias = bs[m][tid];
#pragma unroll
    for (int r = 0; r < 8; r++)
        outs[m][(size_t)(row0 + r) * D_ + tid] = acc[r] + bias;
}

// smem layout for tf32 fuse: two fp32 e-tile buffers + red
#define EROW 132                         // floats per j-row (128 + 4 pad)
#define BUFW (64 * EROW)                 // 8448 words per buffer
#define RED_OFF (2 * BUFW)               // 16896
#define FUSE_WORDS (2 * BUFW + 384)      // 17280 words = 69120 B
#define XS_STRIDE EROW
// XS overlays the current buffer p

// tf32 single-pass mma over one j-tile. NT = 8 (64 rows) or 1 (8 rows).
template <int NT>
__device__ __forceinline__ void mma_tf32(const float* __restrict__ buf,
                                         float acc[8][4], const uint32_t a[16][4],
                                         int g, int tig) {
#pragma unroll
    for (int ks = 0; ks < 16; ks++) {
#pragma unroll
        for (int nt = 0; nt < NT; nt++) {
            const float* row = buf + (8 * nt + g) * EROW + 8 * ks + tig;
            uint32_t b0 = to_tf32(row[0]);
            uint32_t b1 = to_tf32(row[4]);
            mma1688_tf32(acc[nt], a[ks][0], a[ks][1], a[ks][2], a[ks][3], b0, b1);
        }
    }
}

template <int NT>
__device__ __forceinline__ void spill_tile(float* __restrict__ XS, const float acc[8][4],
                                           int arow, int g, int tig) {
#pragma unroll
    for (int nt = 0; nt < NT; nt++) {
        const int jr = 8 * nt + 2 * tig;
        XS[jr * XS_STRIDE + arow] = acc[nt][0];
        XS[(jr + 1) * XS_STRIDE + arow] = acc[nt][1];
        XS[jr * XS_STRIDE + arow + 8] = acc[nt][2];
        XS[(jr + 1) * XS_STRIDE + arow + 8] = acc[nt][3];
    }
}

// ---------------- K2: tf32 single-pass fused kernel -----------------------
// grid = 1600 blocks (one per (b,i)), 256 threads (8 warps).
__global__ void __launch_bounds__(256, 2)
fuse_tf32_kernel(const float* __restrict__ e,
                 const float* __restrict__ Cb,
                 const float* __restrict__ gamma_e, const float* __restrict__ beta_e,
                 const float* __restrict__ gamma_h, const float* __restrict__ beta_h) {
    extern __shared__ float smf[];
    float* red = smf + RED_OFF;
    __shared__ unsigned int s_ticket;

    const int tid = threadIdx.x;
    const int lane = tid & 31;
    const int warp = tid >> 5;     // 0..7
    const int g = lane >> 2;
    const int tig = lane & 3;
    const int arow = warp * 16 + g;
    const int bi = blockIdx.x;
    const int b = bi / N_;
    const int dcol = tid & 127;
    const int jh = tid >> 7;       // 0 or 1

    const float* e_base = e + (size_t)bi * N_ * D_;
    const uint32_t sbase = smem_u32(smf);

    // ---- prologue: issue prefetch of tile 0 into buf0 ----
    {
        const float4* E4 = reinterpret_cast<const float4*>(e_base);
        for (int fid = tid; fid < 2048; fid += 256) {
            const int row = fid >> 5;
            const int k4 = fid & 31;
            CP_ASYNC16(sbase + (row * EROW + 4 * k4) * 4, (const char*)(E4 + fid));
        }
        CP_COMMIT();
    }

    if (tid < 128) {
        red[tid] = 0.0f;
        red[128 + tid] = 0.0f;
        red[256 + tid] = 0.0f;
    }

    // ---- A fragments: Cw tf32, 64 regs, loaded once (L2-hot) ----
    uint32_t a[16][4];
#pragma unroll
    for (int ks = 0; ks < 16; ks++) {
        a[ks][0] = g_CwT[arow * D_ + 8 * ks + tig];
        a[ks][1] = g_CwT[(arow + 8) * D_ + 8 * ks + tig];
        a[ks][2] = g_CwT[arow * D_ + 8 * ks + tig + 4];
        a[ks][3] = g_CwT[(arow + 8) * D_ + 8 * ks + tig + 4];
    }

    __half* xo_base = g_x + (size_t)bi * N_ * D_;
    const float* Ah_b = g_Ah + (size_t)b * N_ * D_;
    const float* Vh_b = g_Vh + (size_t)b * N_ * D_;
    const float Bh_r = g_Bh[(size_t)bi * D_ + dcol];
    const float Cb_r = Cb[dcol];

    float sumv = 0.0f, sqv = 0.0f, aggv = 0.0f;

    for (int t = 0; t < 4; t++) {
        const int p = t & 1;
        const int j0 = t * 64;
        const int jcnt = (t < 3) ? 64 : (N_ - 192);   // 64,64,64,8
        const float* buf = smf + p * BUFW;
        float* XS = smf + p * BUFW;

        CP_WAIT0();
        __syncthreads();   // buf p ready; all threads past column(t-1)

        // ---- issue prefetch(t+1) into buf p^1 (overlaps mma+spill+column) --
        if (t < 3) {
            const int njcnt = (t < 2) ? 64 : (N_ - 192);
            const int nnf4 = njcnt * 32;
            const float4* E4 = reinterpret_cast<const float4*>(e_base) + (t + 1) * 2048;
            const uint32_t dst0 = sbase + ((p ^ 1) * BUFW) * 4;
            for (int fid = tid; fid < nnf4; fid += 256) {
                const int row = fid >> 5;
                const int k4 = fid & 31;
                CP_ASYNC16(dst0 + (row * EROW + 4 * k4) * 4, (const char*)(E4 + fid));
            }
            CP_COMMIT();
        }

        // ---- mma (single tf32 pass) ----
        float acc[8][4];
#pragma unroll
        for (int nt = 0; nt < 8; nt++)
#pragma unroll
            for (int q = 0; q < 4; q++) acc[nt][q] = 0.0f;

        if (t < 3) {
            mma_tf32<8>(buf, acc, a, g, tig);
        } else {
            mma_tf32<1>(buf, acc, a, g, tig);
        }
        __syncthreads();   // mma reads of buf p done

        if (t < 3) {
            spill_tile<8>(XS, acc, arow, g, tig);
        } else {
            spill_tile<1>(XS, acc, arow, g, tig);
        }
        __syncthreads();   // XS ready

        // ---- column pass: thread (dcol, jh), batched prefetch ----
        const int half = jcnt >> 1;
        if (half == 32) {
#pragma unroll
            for (int jj0 = 0; jj0 < 32; jj0 += 8) {
                float xv[8], av[8], vv[8];
#pragma unroll
                for (int u = 0; u < 8; u++) {
                    const int j = jh * 32 + jj0 + u;
                    xv[u] = XS[j * XS_STRIDE + dcol];
                    av[u] = Ah_b[(j0 + j) * D_ + dcol];
                    vv[u] = Vh_b[(j0 + j) * D_ + dcol];
                }
#pragma unroll
                for (int u = 0; u < 8; u++) {
                    const int j = jh * 32 + jj0 + u;
                    float x = xv[u] + Cb_r + Bh_r + av[u];
                    xo_base[(size_t)(j0 + j) * D_ + dcol] = __float2half_rn(x);
                    sumv += x;
                    sqv += x * x;
                    aggv += __fdividef(vv[u], 1.0f + __expf(-x));
                }
            }
        } else {
            for (int jj = 0; jj < half; jj++) {
                const int j = jh * half + jj;
                float x = XS[j * XS_STRIDE + dcol] + Cb_r + Bh_r + Ah_b[(j0 + j) * D_ + dcol];
                xo_base[(size_t)(j0 + j) * D_ + dcol] = __float2half_rn(x);
                sumv += x;
                sqv += x * x;
                aggv += __fdividef(Vh_b[(j0 + j) * D_ + dcol], 1.0f + __expf(-x));
            }
        }
    }

    // ---- merge the two j-halves, then one global update per d ----
    __syncthreads();
    atomicAdd(&red[dcol], aggv);
    atomicAdd(&red[128 + dcol], sumv);
    atomicAdd(&red[256 + dcol], sqv);
    __syncthreads();

    if (tid < 128) {
        const int d = tid;
        float hn = g_Uh[(size_t)bi * D_ + d] + red[d];
        g_hnew[(size_t)bi * D_ + d] = hn;
        atomicAdd(&g_acc[0 * D_ + d], red[128 + d]);
        atomicAdd(&g_acc[1 * D_ + d], red[256 + d]);
        atomicAdd(&g_acc[2 * D_ + d], hn);
        atomicAdd(&g_acc[3 * D_ + d], hn * hn);
    }

    // ---- last block computes BN coefficients (fused finalize) ----
    __threadfence();
    __syncthreads();
    if (tid == 0) s_ticket = atomicAdd(&g_done, 1u);
    __syncthreads();
    if (s_ticket == BN_ - 1 && tid < 128) {
        const int d = tid;
        const float Ne = (float)B_ * N_ * N_;
        float mu = g_acc[d] / Ne;
        float var = g_acc[D_ + d] / Ne - mu * mu;
        float sc = rsqrtf(var + EPS) * gamma_e[d];
        g_coef[d] = sc;
        g_coef[D_ + d] = beta_e[d] - mu * sc;

        const float Nh = (float)B_ * N_;
        float muh = g_acc[2 * D_ + d] / Nh;
        float varh = g_acc[3 * D_ + d] / Nh - muh * muh;
        float sch = rsqrtf(varh + EPS) * gamma_h[d];
        g_coef[2 * D_ + d] = sch;
        g_coef[3 * D_ + d] = beta_h[d] - muh * sch;
    }
}

// ---------------- K3: combined epilogue (e blocks then h blocks) ----------
__global__ void final_kernel(const float* __restrict__ e_in, const float* __restrict__ h_in,
                             float* __restrict__ e_out, float* __restrict__ h_out) {
    const int blk = blockIdx.x;
    if (blk < EBLKS) {
        size_t idx = (size_t)blk * 256 + threadIdx.x;   // float4 index
        int d4 = (int)(idx & 31);
        float4 sc = reinterpret_cast<const float4*>(g_coef)[d4];
        float4 sh = reinterpret_cast<const float4*>(g_coef + D_)[d4];
        uint2 xraw = *(reinterpret_cast<const uint2*>(g_x) + idx);
        __half2 xh0 = *reinterpret_cast<__half2*>(&xraw.x);
        __half2 xh1 = *reinterpret_cast<__half2*>(&xraw.y);
        float4 ei = reinterpret_cast<const float4*>(e_in)[idx];
        float4 r;
        r.x = ei.x + fmaxf(0.0f, __low2float(xh0) * sc.x + sh.x);
        r.y = ei.y + fmaxf(0.0f, __high2float(xh0) * sc.y + sh.y);
        r.z = ei.z + fmaxf(0.0f, __low2float(xh1) * sc.z + sh.z);
        r.w = ei.w + fmaxf(0.0f, __high2float(xh1) * sc.w + sh.w);
        reinterpret_cast<float4*>(e_out)[idx] = r;
    } else {
        size_t idx = (size_t)(blk - EBLKS) * 256 + threadIdx.x;
        int d4 = (int)(idx & 31);
        float4 sc = reinterpret_cast<const float4*>(g_coef + 2 * D_)[d4];
        float4 sh = reinterpret_cast<const float4*>(g_coef + 3 * D_)[d4];
        float4 x = reinterpret_cast<const float4*>(g_hnew)[idx];
        float4 hi = reinterpret_cast<const float4*>(h_in)[idx];
        float4 r;
        r.x = hi.x + fmaxf(0.0f, x.x * sc.x + sh.x);
        r.y = hi.y + fmaxf(0.0f, x.y * sc.y + sh.y);
        r.z = hi.z + fmaxf(0.0f, x.z * sc.z + sh.z);
        r.w = hi.w + fmaxf(0.0f, x.w * sc.w + sh.w);
        reinterpret_cast<float4*>(h_out)[idx] = r;
    }
}

// ---------------- launch ---------------------------------------------------
extern "C" void kernel_launch(void* const* d_in, const int* in_sizes, int n_in,
                              void* d_out, int out_size) {
    const float* h = (const float*)d_in[0];
    const float* e = (const float*)d_in[1];
    const float* Uw = (const float*)d_in[2];
    const float* Ub = (const float*)d_in[3];
    const float* Vw = (const float*)d_in[4];
    const float* Vb = (const float*)d_in[5];
    const float* Aw = (const float*)d_in[6];
    const float* Ab = (const float*)d_in[7];
    const float* Bw = (const float*)d_in[8];
    const float* Bb = (const float*)d_in[9];
    const float* Cw = (const float*)d_in[10];
    const float* Cb = (const float*)d_in[11];
    const float* gamma_h = (const float*)d_in[12];
    const float* beta_h = (const float*)d_in[13];
    const float* gamma_e = (const float*)d_in[14];
    const float* beta_e = (const float*)d_in[15];

    float* out = (float*)d_out;
    float* h_out = out;          // [B,N,D]
    float* e_out = out + HSZ;    // [B,N,N,D]

    static int attr_done = 0;
    const int fuse_smem = FUSE_WORDS * 4;       // 69120 B
    if (!attr_done) {
        cudaFuncSetAttribute(fuse_tf32_kernel, cudaFuncAttributeMaxDynamicSharedMemorySize, fuse_smem);
        attr_done = 1;
    }

    proj_setup_kernel<<<817, 128>>>(h, Uw, Ub, Vw, Vb, Aw, Ab, Bw, Bb, Cw);
    fuse_tf32_kernel<<<BN_, 256, fuse_smem>>>(e, Cb, gamma_e, beta_e, gamma_h, beta_h);
    final_kernel<<<EBLKS + HBLKS, 256>>>(e, h, e_out, h_out);
}